// round 6
// baseline (speedup 1.0000x reference)
#include <cuda_runtime.h>
#include <cuda_bf16.h>

#define NPTS 80000          // 100*100*8
#define NG 1025             // 1024 gaussians + 1 synthetic "empty"
#define NC 18
#define THREADS 256
#define CAP 128             // staged window; covers all observed blocks

// Block tile: 4h x 4w x 8d = 128 points. 2 threads per point (gaussian-split).
// pt = tid & 127: dd = pt&7, ww = (pt>>3)&3, hh = pt>>5. half = tid>>7.

// rec row (16 floats): [0..2]=mu [3]=rx | [4]=ry [5]=rz [6]=lopa [7]=a00
//                      [8]=a01 [9]=a02 [10]=a11 [11]=a12 | [12]=a22
// a_ij carry -0.5 and off-diagonal 2x folded in:
//   arg = lopa + a00 dx^2 + a11 dy^2 + a22 dz^2 + a01 dxdy + a02 dxdz + a12 dydz

__device__ __forceinline__ void stage_gaussian(
    int slot, int g,
    float mux, float muy, float muz, float s0, float s1, float s2,
    const float* __restrict__ rots, const float* __restrict__ opac,
    const float* __restrict__ feats, const float* __restrict__ empty_scalar,
    float* __restrict__ s_rec, float* __restrict__ s_ft)
{
    float* rc = s_rec + slot * 16;
    float* ft = s_ft + slot * 20;
    if (g < NG - 1) {
        float qw = __ldg(rots + g * 4 + 0), qx = __ldg(rots + g * 4 + 1);
        float qy = __ldg(rots + g * 4 + 2), qz = __ldg(rots + g * 4 + 3);
        const float* fs = feats + (size_t)g * (NC - 1);
        #pragma unroll
        for (int c = 0; c < NC - 1; c++) ft[c] = __ldg(fs + c);
        ft[NC - 1] = 0.f;

        float inv = rsqrtf(qw * qw + qx * qx + qy * qy + qz * qz);
        qw *= inv; qx *= inv; qy *= inv; qz *= inv;
        float R00 = 1.f - 2.f * (qy * qy + qz * qz);
        float R01 = 2.f * (qx * qy - qw * qz);
        float R02 = 2.f * (qx * qz + qw * qy);
        float R10 = 2.f * (qx * qy + qw * qz);
        float R11 = 1.f - 2.f * (qx * qx + qz * qz);
        float R12 = 2.f * (qy * qz - qw * qx);
        float R20 = 2.f * (qx * qz - qw * qy);
        float R21 = 2.f * (qy * qz + qw * qx);
        float R22 = 1.f - 2.f * (qx * qx + qy * qy);

        float s0q = s0 * s0, s1q = s1 * s1, s2q = s2 * s2;
        float a  = s0q * R00 * R00 + s1q * R01 * R01 + s2q * R02 * R02;
        float b  = s0q * R00 * R10 + s1q * R01 * R11 + s2q * R02 * R12;
        float c  = s0q * R00 * R20 + s1q * R01 * R21 + s2q * R02 * R22;
        float dd_ = s0q * R10 * R10 + s1q * R11 * R11 + s2q * R12 * R12;
        float e  = s0q * R10 * R20 + s1q * R11 * R21 + s2q * R12 * R22;
        float f  = s0q * R20 * R20 + s1q * R21 * R21 + s2q * R22 * R22;

        float det = a * (dd_ * f - e * e) - b * (b * f - e * c) + c * (b * e - dd_ * c);
        float idet = 1.0f / det;

        rc[0] = mux; rc[1] = muy; rc[2] = muz;
        rc[3] = 3.f * s0; rc[4] = 3.f * s1; rc[5] = 3.f * s2;
        rc[6] = __logf(__ldg(opac + g));
        rc[7]  = -0.5f * (dd_ * f - e * e) * idet;   // a00
        rc[8]  = -(c * e - b * f) * idet;            // a01 (2x folded)
        rc[9]  = -(b * e - c * dd_) * idet;          // a02
        rc[10] = -0.5f * (a * f - c * c) * idet;     // a11
        rc[11] = -(b * c - a * e) * idet;            // a12
        rc[12] = -0.5f * (a * dd_ - b * b) * idet;   // a22
    } else {
        rc[0] = 0.f; rc[1] = 0.f; rc[2] = 2.2f;
        rc[3] = 240.f; rc[4] = 240.f; rc[5] = 19.2f;
        rc[6] = 0.f;
        rc[7]  = -0.5f / 6400.f;
        rc[8]  = 0.f; rc[9] = 0.f;
        rc[10] = -0.5f / 6400.f;
        rc[11] = 0.f;
        rc[12] = -0.5f / 40.96f;
        #pragma unroll
        for (int c = 0; c < NC - 1; c++) ft[c] = 0.f;
        ft[NC - 1] = __ldg(empty_scalar);
    }
}

__global__ __launch_bounds__(THREADS) void voxelize(
    const float* __restrict__ means,
    const float* __restrict__ opac,
    const float* __restrict__ scales,
    const float* __restrict__ rots,
    const float* __restrict__ feats,
    const float* __restrict__ empty_scalar,
    float* __restrict__ out)
{
    const int tid = threadIdx.x;
    const int lane = tid & 31;
    const int pt = tid & 127;
    const int half = tid >> 7;
    const int bh = blockIdx.x, bw = blockIdx.y;
    const int dd = pt & 7;
    const int ww = (pt >> 3) & 3;
    const int hh = pt >> 5;
    const int h = 4 * bh + hh;
    const int w = 4 * bw + ww;
    const int p = h * 800 + w * 8 + dd;

    // match reference rounding
    const float px = __fadd_rn(__fmul_rn((float)h + 0.5f, 0.8f), -40.f);
    const float py = __fadd_rn(__fmul_rn((float)w + 0.5f, 0.8f), -40.f);
    const float pz = __fadd_rn(__fmul_rn((float)dd + 0.5f, 0.8f), -1.f);

    const float EPS = 1e-3f;
    const float bcx = (4.f * (float)bh + 2.f) * 0.8f - 40.f;   // half 1.2
    const float bcy = (4.f * (float)bw + 2.f) * 0.8f - 40.f;   // half 1.2
    const float BH  = 1.2f + EPS;
    const float BHZ = 2.8f + EPS;                               // z center 2.2

    __shared__ unsigned short s_list[NG + 1];
    __shared__ int s_cnt;
    __shared__ __align__(16) float s_rec[CAP * 16];
    __shared__ __align__(16) float s_ft[CAP * 20];
    if (tid == 0) s_cnt = 0;
    __syncthreads();

    // ---- fused compaction + staging ----
    {
        float mx[4], my[4], mz[4], sx[4], sy[4], sz[4];
        #pragma unroll
        for (int it = 0; it < 4; it++) {
            const int g = tid + it * 256;          // < 1024
            mx[it] = __ldg(means + 3 * g);
            my[it] = __ldg(means + 3 * g + 1);
            mz[it] = __ldg(means + 3 * g + 2);
            sx[it] = __ldg(scales + 3 * g);
            sy[it] = __ldg(scales + 3 * g + 1);
            sz[it] = __ldg(scales + 3 * g + 2);
        }
        #pragma unroll
        for (int it = 0; it < 4; it++) {
            const int g = tid + it * 256;
            if (fabsf(bcx - mx[it]) <= BH + 3.f * sx[it] &&
                fabsf(bcy - my[it]) <= BH + 3.f * sy[it] &&
                fabsf(2.2f - mz[it]) <= BHZ + 3.f * sz[it]) {
                const int slot = atomicAdd(&s_cnt, 1);
                s_list[slot] = (unsigned short)g;
                if (slot < CAP)
                    stage_gaussian(slot, g, mx[it], my[it], mz[it],
                                   sx[it], sy[it], sz[it],
                                   rots, opac, feats, empty_scalar, s_rec, s_ft);
            }
        }
        if (tid == 0) {   // synthetic gaussian always overlaps
            const int slot = atomicAdd(&s_cnt, 1);
            s_list[slot] = (unsigned short)(NG - 1);
            if (slot < CAP)
                stage_gaussian(slot, NG - 1, 0.f, 0.f, 2.2f, 0.f, 0.f, 0.f,
                               rots, opac, feats, empty_scalar, s_rec, s_ft);
        }
    }
    __syncthreads();
    const int cnt = s_cnt;

    float acc[NC];
    #pragma unroll
    for (int c = 0; c < NC; c++) acc[c] = 0.f;

    for (int t0 = 0; ; t0 += CAP) {
        const int n = min(CAP, cnt - t0);

        if (t0 > 0) {   // overflow restaging (effectively never taken)
            if (tid < n) {
                const int g = s_list[t0 + tid];
                float mux = 0.f, muy = 0.f, muz = 2.2f, s0 = 0.f, s1 = 0.f, s2 = 0.f;
                if (g < NG - 1) {
                    mux = __ldg(means + 3 * g); muy = __ldg(means + 3 * g + 1);
                    muz = __ldg(means + 3 * g + 2);
                    s0 = __ldg(scales + 3 * g); s1 = __ldg(scales + 3 * g + 1);
                    s2 = __ldg(scales + 3 * g + 2);
                }
                stage_gaussian(tid, g, mux, muy, muz, s0, s1, s2,
                               rots, opac, feats, empty_scalar, s_rec, s_ft);
            }
            __syncthreads();
        }

        // ---- eval: halves take interleaved 32-chunks for balance ----
        for (int base = 32 * half; base < n; base += 64) {
            const int s = base + lane;
            bool ok = false;
            if (s < n) {
                const float4 v0 = *(const float4*)(s_rec + s * 16);      // mu, rx
                const float4 v1 = *(const float4*)(s_rec + s * 16 + 4);  // ry, rz, lopa, a00
                ok = (fabsf(px   - v0.x) <= v0.w + EPS) &&               // warp x spread = 0
                     (fabsf(bcy  - v0.y) <= BH   + v1.x) &&
                     (fabsf(2.2f - v0.z) <= BHZ  + v1.y);
            }
            unsigned mbits = __ballot_sync(0xFFFFFFFFu, ok);
            while (mbits) {
                const int j = base + (__ffs(mbits) - 1);
                mbits &= mbits - 1;
                const float4 v0 = *(const float4*)(s_rec + j * 16);
                const float4 v1 = *(const float4*)(s_rec + j * 16 + 4);
                const float dx = px - v0.x;
                const float dy = py - v0.y;
                const float dz = pz - v0.z;
                if (fabsf(dx) <= v0.w && fabsf(dy) <= v1.x && fabsf(dz) <= v1.y) {
                    const float4 v2 = *(const float4*)(s_rec + j * 16 + 8);  // a01,a02,a11,a12
                    const float a22 = s_rec[j * 16 + 12];
                    float t1 = fmaf(v2.x, dy, v1.w * dx);      // a00 dx + a01 dy
                    t1 = fmaf(v2.y, dz, t1);                   // + a02 dz
                    const float t2 = fmaf(v2.w, dz, v2.z * dy);// a11 dy + a12 dz
                    float arg = fmaf(a22 * dz, dz, v1.z);      // lopa + a22 dz^2
                    arg = fmaf(dy, t2, arg);
                    arg = fmaf(dx, t1, arg);
                    const float wgt = __expf(arg);
                    const float* ft = s_ft + j * 20;
                    #pragma unroll
                    for (int q = 0; q < 4; q++) {
                        const float4 fv = *(const float4*)(ft + 4 * q);
                        acc[4 * q + 0] = fmaf(wgt, fv.x, acc[4 * q + 0]);
                        acc[4 * q + 1] = fmaf(wgt, fv.y, acc[4 * q + 1]);
                        acc[4 * q + 2] = fmaf(wgt, fv.z, acc[4 * q + 2]);
                        acc[4 * q + 3] = fmaf(wgt, fv.w, acc[4 * q + 3]);
                    }
                    const float2 fv2 = *(const float2*)(ft + 16);
                    acc[16] = fmaf(wgt, fv2.x, acc[16]);
                    acc[17] = fmaf(wgt, fv2.y, acc[17]);
                }
            }
        }

        if (t0 + CAP >= cnt) break;
        __syncthreads();   // protect s_rec/s_ft before restaging
    }
    __syncthreads();

    // ---- cross-half reduction through s_ft (2560 floats >= 128*18) ----
    if (half == 1) {
        float* r = s_ft + pt * NC;
        #pragma unroll
        for (int c = 0; c < NC; c++) r[c] = acc[c];
    }
    __syncthreads();
    if (half == 0) {
        const float* r = s_ft + pt * NC;
        out[p] = 0.f;   // grid_density
        float2* o = (float2*)(out + NPTS + (size_t)p * NC);
        #pragma unroll
        for (int c2 = 0; c2 < NC / 2; c2++)
            o[c2] = make_float2(acc[2 * c2] + r[2 * c2],
                                acc[2 * c2 + 1] + r[2 * c2 + 1]);
    }
}

extern "C" void kernel_launch(void* const* d_in, const int* in_sizes, int n_in,
                              void* d_out, int out_size) {
    const float* means        = (const float*)d_in[0];
    const float* opacities    = (const float*)d_in[1];
    const float* scales       = (const float*)d_in[2];
    const float* rotations    = (const float*)d_in[3];
    const float* features     = (const float*)d_in[4];
    const float* empty_scalar = (const float*)d_in[5];
    float* out = (float*)d_out;

    dim3 grid(25, 25);
    voxelize<<<grid, THREADS>>>(means, opacities, scales, rotations,
                                features, empty_scalar, out);
}

// round 7
// speedup vs baseline: 1.1604x; 1.1604x over previous
#include <cuda_runtime.h>
#include <cuda_bf16.h>

#define NPTS 80000          // 100*100*8
#define NG 1025             // 1024 gaussians + 1 synthetic "empty"
#define NC 18
#define THREADS 256
#define TILE 64

// Block tile: 4h x 4w x 8d = 128 points. 2 threads per point (gaussian-split).
// pt = tid & 127: dd = pt&7, ww = (pt>>3)&3, hh = pt>>5. half = tid>>7.

__global__ __launch_bounds__(THREADS, 4) void voxelize(
    const float* __restrict__ means,
    const float* __restrict__ opac,
    const float* __restrict__ scales,
    const float* __restrict__ rots,
    const float* __restrict__ feats,
    const float* __restrict__ empty_scalar,
    float* __restrict__ out)
{
    const int tid = threadIdx.x;
    const int pt = tid & 127;
    const int half = tid >> 7;
    const int bh = blockIdx.x, bw = blockIdx.y;
    const int dd = pt & 7;
    const int ww = (pt >> 3) & 3;
    const int hh = pt >> 5;
    const int h = 4 * bh + hh;
    const int w = 4 * bw + ww;
    const int p = h * 800 + w * 8 + dd;

    // match reference rounding: (i+0.5)*0.8 + lo, no fma contraction
    const float px = __fadd_rn(__fmul_rn((float)h + 0.5f, 0.8f), -40.f);
    const float py = __fadd_rn(__fmul_rn((float)w + 0.5f, 0.8f), -40.f);
    const float pz = __fadd_rn(__fmul_rn((float)dd + 0.5f, 0.8f), -1.f);

    // analytic block bbox (conservative, eps-padded); z center 2.2, half 2.8
    const float EPS = 1e-3f;
    const float bcx = (4.f * (float)bh + 2.f) * 0.8f - 40.f;   // half 1.2
    const float bcy = (4.f * (float)bw + 2.f) * 0.8f - 40.f;   // half 1.2
    const float BH  = 1.2f + EPS;
    const float BHZ = 2.8f + EPS;

    __shared__ unsigned short s_list[NG + 1];
    __shared__ int s_cnt;
    if (tid == 0) s_cnt = 0;
    __syncthreads();

    // ---- block-level compaction (4 unrolled iters, 24 LDGs in flight) ----
    {
        float mx[4], my[4], mz[4], sx[4], sy[4], sz[4];
        #pragma unroll
        for (int it = 0; it < 4; it++) {
            const int g = tid + it * 256;          // < 1024 always
            mx[it] = __ldg(means + 3 * g);
            my[it] = __ldg(means + 3 * g + 1);
            mz[it] = __ldg(means + 3 * g + 2);
            sx[it] = __ldg(scales + 3 * g);
            sy[it] = __ldg(scales + 3 * g + 1);
            sz[it] = __ldg(scales + 3 * g + 2);
        }
        #pragma unroll
        for (int it = 0; it < 4; it++) {
            const int g = tid + it * 256;
            if (fabsf(bcx - mx[it]) <= BH + 3.f * sx[it] &&
                fabsf(bcy - my[it]) <= BH + 3.f * sy[it] &&
                fabsf(2.2f - mz[it]) <= BHZ + 3.f * sz[it]) {
                s_list[atomicAdd(&s_cnt, 1)] = (unsigned short)g;
            }
        }
        if (tid == 0)   // synthetic gaussian covers the whole volume: always in
            s_list[atomicAdd(&s_cnt, 1)] = (unsigned short)(NG - 1);
    }
    __syncthreads();
    const int cnt = s_cnt;

    // rec layout (16 floats/row): [0..2]=mu [3]=rx | [4]=ry [5]=rz [6]=lopa [7]=a00
    //   [8]=a01 [9]=a02 [10]=a11 [11]=a12 | [12]=a22
    // a_ij carry -0.5 and off-diagonal 2x folded in:
    //   arg = lopa + a00 dx^2 + a11 dy^2 + a22 dz^2 + a01 dxdy + a02 dxdz + a12 dydz
    // s_pool aliases: [0, TILE*16) = s_rec; [TILE*16, TILE*36) = s_ft rows of 20.
    // After the tile loop the pool (2304 floats = 128*18) is the reduction buffer.
    __shared__ __align__(16) float s_pool[TILE * 36];
    float* const s_rec = s_pool;                 // [TILE][16]
    float* const s_ft  = s_pool + TILE * 16;     // [TILE][20]

    float acc[NC];
    #pragma unroll
    for (int c = 0; c < NC; c++) acc[c] = 0.f;

    for (int t0 = 0; t0 < cnt; t0 += TILE) {
        const int n = min(TILE, cnt - t0);

        // ---- dense staging phase: tid<n -> record; 128<=tid<128+n -> feats ----
        if (tid < n) {
            const int g = s_list[t0 + tid];
            float* rc = s_rec + tid * 16;
            if (g < NG - 1) {
                float qw = __ldg(rots + g * 4 + 0), qx = __ldg(rots + g * 4 + 1);
                float qy = __ldg(rots + g * 4 + 2), qz = __ldg(rots + g * 4 + 3);
                float inv = rsqrtf(qw * qw + qx * qx + qy * qy + qz * qz);
                qw *= inv; qx *= inv; qy *= inv; qz *= inv;
                float R00 = 1.f - 2.f * (qy * qy + qz * qz);
                float R01 = 2.f * (qx * qy - qw * qz);
                float R02 = 2.f * (qx * qz + qw * qy);
                float R10 = 2.f * (qx * qy + qw * qz);
                float R11 = 1.f - 2.f * (qx * qx + qz * qz);
                float R12 = 2.f * (qy * qz - qw * qx);
                float R20 = 2.f * (qx * qz - qw * qy);
                float R21 = 2.f * (qy * qz + qw * qx);
                float R22 = 1.f - 2.f * (qx * qx + qy * qy);

                float s0 = __ldg(scales + g * 3 + 0);
                float s1 = __ldg(scales + g * 3 + 1);
                float s2 = __ldg(scales + g * 3 + 2);
                float s0q = s0 * s0, s1q = s1 * s1, s2q = s2 * s2;

                float a  = s0q * R00 * R00 + s1q * R01 * R01 + s2q * R02 * R02;
                float b  = s0q * R00 * R10 + s1q * R01 * R11 + s2q * R02 * R12;
                float c  = s0q * R00 * R20 + s1q * R01 * R21 + s2q * R02 * R22;
                float dd_ = s0q * R10 * R10 + s1q * R11 * R11 + s2q * R12 * R12;
                float e  = s0q * R10 * R20 + s1q * R11 * R21 + s2q * R12 * R22;
                float f  = s0q * R20 * R20 + s1q * R21 * R21 + s2q * R22 * R22;

                float det = a * (dd_ * f - e * e) - b * (b * f - e * c) + c * (b * e - dd_ * c);
                float idet = 1.0f / det;

                rc[0] = __ldg(means + g * 3 + 0);
                rc[1] = __ldg(means + g * 3 + 1);
                rc[2] = __ldg(means + g * 3 + 2);
                rc[3] = 3.f * s0;
                rc[4] = 3.f * s1;
                rc[5] = 3.f * s2;
                rc[6] = __logf(__ldg(opac + g));
                rc[7]  = -0.5f * (dd_ * f - e * e) * idet;   // a00
                rc[8]  = -(c * e - b * f) * idet;            // a01 (2x folded)
                rc[9]  = -(b * e - c * dd_) * idet;          // a02
                rc[10] = -0.5f * (a * f - c * c) * idet;     // a11
                rc[11] = -(b * c - a * e) * idet;            // a12
                rc[12] = -0.5f * (a * dd_ - b * b) * idet;   // a22
            } else {
                rc[0] = 0.f; rc[1] = 0.f; rc[2] = 2.2f;
                rc[3] = 240.f; rc[4] = 240.f; rc[5] = 19.2f;
                rc[6] = 0.f;
                rc[7]  = -0.5f / 6400.f;
                rc[8]  = 0.f; rc[9] = 0.f;
                rc[10] = -0.5f / 6400.f;
                rc[11] = 0.f;
                rc[12] = -0.5f / 40.96f;
            }
        } else if (tid >= 128 && tid < 128 + n) {
            const int s = tid - 128;
            const int g = s_list[t0 + s];
            float* ft = s_ft + s * 20;
            if (g < NG - 1) {
                const float* fs = feats + (size_t)g * (NC - 1);
                #pragma unroll
                for (int c = 0; c < NC - 1; c++) ft[c] = __ldg(fs + c);
                ft[NC - 1] = 0.f;
            } else {
                #pragma unroll
                for (int c = 0; c < NC - 1; c++) ft[c] = 0.f;
                ft[NC - 1] = __ldg(empty_scalar);
            }
        }
        __syncthreads();

        // ---- eval: straight predicated loop over this half's entries ----
        // No ballot, no branch: every entry costs the same, so a contiguous
        // split is balanced and the compiler can pipeline across iterations.
        const int nh = (n + 1) >> 1;
        const int lo = half * nh;
        const int hi = min(n, lo + nh);
        #pragma unroll 2
        for (int j = lo; j < hi; j++) {
            const float4 v0 = *(const float4*)(s_rec + j * 16);      // mu, rx
            const float4 v1 = *(const float4*)(s_rec + j * 16 + 4);  // ry,rz,lopa,a00
            const float dx = px - v0.x;
            const float dy = py - v0.y;
            const float dz = pz - v0.z;
            const bool m = (fabsf(dx) <= v0.w) & (fabsf(dy) <= v1.x) &
                           (fabsf(dz) <= v1.y);
            const float4 v2 = *(const float4*)(s_rec + j * 16 + 8);  // a01,a02,a11,a12
            const float a22 = s_rec[j * 16 + 12];
            float t1 = fmaf(v2.x, dy, v1.w * dx);        // a00 dx + a01 dy
            t1 = fmaf(v2.y, dz, t1);                     // + a02 dz
            const float t2 = fmaf(v2.w, dz, v2.z * dy);  // a11 dy + a12 dz
            float arg = fmaf(a22 * dz, dz, v1.z);        // lopa + a22 dz^2
            arg = fmaf(dy, t2, arg);
            arg = fmaf(dx, t1, arg);
            const float wgt = m ? __expf(arg) : 0.f;
            const float* ft = s_ft + j * 20;
            #pragma unroll
            for (int q = 0; q < 4; q++) {
                const float4 fv = *(const float4*)(ft + 4 * q);
                acc[4 * q + 0] = fmaf(wgt, fv.x, acc[4 * q + 0]);
                acc[4 * q + 1] = fmaf(wgt, fv.y, acc[4 * q + 1]);
                acc[4 * q + 2] = fmaf(wgt, fv.z, acc[4 * q + 2]);
                acc[4 * q + 3] = fmaf(wgt, fv.w, acc[4 * q + 3]);
            }
            const float2 fv2 = *(const float2*)(ft + 16);
            acc[16] = fmaf(wgt, fv2.x, acc[16]);
            acc[17] = fmaf(wgt, fv2.y, acc[17]);
        }
        __syncthreads();
    }

    // ---- cross-half reduction through the (now dead) staging pool ----
    if (half == 1) {
        float* r = s_pool + pt * NC;
        #pragma unroll
        for (int c = 0; c < NC; c++) r[c] = acc[c];
    }
    __syncthreads();
    if (half == 0) {
        const float* r = s_pool + pt * NC;
        out[p] = 0.f;   // grid_density
        float2* o = (float2*)(out + NPTS + (size_t)p * NC);
        #pragma unroll
        for (int c2 = 0; c2 < NC / 2; c2++)
            o[c2] = make_float2(acc[2 * c2] + r[2 * c2],
                                acc[2 * c2 + 1] + r[2 * c2 + 1]);
    }
}

extern "C" void kernel_launch(void* const* d_in, const int* in_sizes, int n_in,
                              void* d_out, int out_size) {
    const float* means        = (const float*)d_in[0];
    const float* opacities    = (const float*)d_in[1];
    const float* scales       = (const float*)d_in[2];
    const float* rotations    = (const float*)d_in[3];
    const float* features     = (const float*)d_in[4];
    const float* empty_scalar = (const float*)d_in[5];
    float* out = (float*)d_out;

    dim3 grid(25, 25);
    voxelize<<<grid, THREADS>>>(means, opacities, scales, rotations,
                                features, empty_scalar, out);
}